// round 1
// baseline (speedup 1.0000x reference)
#include <cuda_runtime.h>

#define BB 128
#define LCDIM 256
#define LEDIM 1024
#define DDIM 256
#define MMDIM 512
#define NEGV -1e9f

// ---------------- scratch (__device__ globals; no allocation allowed) -------
__device__ float g_c[(size_t)BB * LCDIM * DDIM];      // c, later tmp1
__device__ float g_e[(size_t)BB * LEDIM * DDIM];      // e, later tmp2
__device__ float g_align[(size_t)BB * LCDIM * LEDIM]; // align, then alpha (in-place)
__device__ float g_beta[(size_t)BB * LCDIM * LEDIM];  // beta
__device__ float g_attc[(size_t)BB * LCDIM * DDIM];
__device__ float g_atte[(size_t)BB * LEDIM * DDIM];
__device__ float g_r1p[BB * 4 * DDIM];
__device__ float g_r2p[BB * 4 * DDIM];

// ---------------- generic strided batched GEMM ------------------------------
// C[M,N] (row-major, ldc=N) = epilogue(A @ B), element access:
//   A[m*sAm + k*sAk], B[k*sBk + n*sBn]; batch via blockIdx.z strides.
// All M,N multiples of 128 and K multiples of 8 in this problem (no bounds).
#define BM 128
#define BN 128
#define BK 8
#define TM 8
#define TN 8

__global__ __launch_bounds__(256) void gemm_k(
    const float* __restrict__ A, const float* __restrict__ B,
    const float* __restrict__ bias, float* __restrict__ C,
    int M, int N, int K,
    long sAm, long sAk, long bsA,
    long sBk, long sBn, long bsB,
    long bsC, int accum, int do_relu)
{
    A += (long)blockIdx.z * bsA;
    B += (long)blockIdx.z * bsB;
    C += (long)blockIdx.z * bsC;

    __shared__ float As[BK][BM];
    __shared__ float Bs[BK][BN];

    const int tid = threadIdx.x;
    const int m0 = blockIdx.y * BM;
    const int n0 = blockIdx.x * BN;
    const int tr = tid >> 4;   // 0..15
    const int tc = tid & 15;   // 0..15

    float acc[TM][TN];
#pragma unroll
    for (int i = 0; i < TM; i++)
#pragma unroll
        for (int j = 0; j < TN; j++) acc[i][j] = 0.f;

    for (int k0 = 0; k0 < K; k0 += BK) {
        // load A tile (pick mapping so the stride-1 dim is fastest across tid)
#pragma unroll
        for (int i = 0; i < (BM * BK) / 256; i++) {
            int idx = tid + i * 256;
            int m, k;
            if (sAk == 1) { k = idx & (BK - 1); m = idx >> 3; }
            else          { m = idx & (BM - 1); k = idx >> 7; }
            As[k][m] = A[(long)(m0 + m) * sAm + (long)(k0 + k) * sAk];
        }
        // load B tile
#pragma unroll
        for (int i = 0; i < (BN * BK) / 256; i++) {
            int idx = tid + i * 256;
            int k, n;
            if (sBn == 1) { n = idx & (BN - 1); k = idx >> 7; }
            else          { k = idx & (BK - 1); n = idx >> 3; }
            Bs[k][n] = B[(long)(k0 + k) * sBk + (long)(n0 + n) * sBn];
        }
        __syncthreads();

#pragma unroll
        for (int k = 0; k < BK; k++) {
            float a[TM], bb[TN];
#pragma unroll
            for (int i = 0; i < TM; i++) a[i] = As[k][tr * TM + i];
#pragma unroll
            for (int j = 0; j < TN; j++) bb[j] = Bs[k][tc * TN + j];
#pragma unroll
            for (int i = 0; i < TM; i++)
#pragma unroll
                for (int j = 0; j < TN; j++)
                    acc[i][j] += a[i] * bb[j];
        }
        __syncthreads();
    }

#pragma unroll
    for (int i = 0; i < TM; i++) {
        int m = m0 + tr * TM + i;
#pragma unroll
        for (int j = 0; j < TN; j++) {
            int n = n0 + tc * TN + j;
            long cidx = (long)m * N + n;
            float v = acc[i][j];
            if (accum) v += C[cidx];
            if (bias)  v += bias[n];
            if (do_relu) v = fmaxf(v, 0.f);
            C[cidx] = v;
        }
    }
}

// ---------------- softmax over Le (axis=2), masked by ehr_mask, IN-PLACE ----
// one block per (b,l) row of LE=1024; 256 threads x 4 values in registers
__global__ __launch_bounds__(256) void alpha_kernel(float* __restrict__ align,
                                                    const int* __restrict__ em)
{
    int b = blockIdx.x / LCDIM;
    long base = (long)blockIdx.x * LEDIM;
    int t = threadIdx.x;

    float v[4];
    float mx = -3.4e38f;
#pragma unroll
    for (int i = 0; i < 4; i++) {
        int e = t + i * 256;
        float x = align[base + e];
        if (em[b * LEDIM + e] == 0) x += NEGV;
        v[i] = x;
        mx = fmaxf(mx, x);
    }
    __shared__ float red[256];
    red[t] = mx; __syncthreads();
    for (int s = 128; s > 0; s >>= 1) { if (t < s) red[t] = fmaxf(red[t], red[t + s]); __syncthreads(); }
    mx = red[0]; __syncthreads();

    float sm = 0.f;
#pragma unroll
    for (int i = 0; i < 4; i++) { v[i] = __expf(v[i] - mx); sm += v[i]; }
    red[t] = sm; __syncthreads();
    for (int s = 128; s > 0; s >>= 1) { if (t < s) red[t] += red[t + s]; __syncthreads(); }
    float inv = 1.f / red[0];

#pragma unroll
    for (int i = 0; i < 4; i++) align[base + t + i * 256] = v[i] * inv;
}

// ---------------- softmax over Lc (axis=1), masked by criteria_mask ---------
// one thread per column e; consecutive threads -> consecutive e (coalesced)
__global__ __launch_bounds__(256) void beta_kernel(const float* __restrict__ align,
                                                   float* __restrict__ beta,
                                                   const int* __restrict__ cm)
{
    int b = blockIdx.x / (LEDIM / 256);
    int e = (blockIdx.x % (LEDIM / 256)) * 256 + threadIdx.x;

    __shared__ float negs[LCDIM];
    for (int l = threadIdx.x; l < LCDIM; l += 256)
        negs[l] = cm[b * LCDIM + l] ? 0.f : NEGV;
    __syncthreads();

    const float* col = align + (long)b * LCDIM * LEDIM + e;
    float mx = -3.4e38f;
#pragma unroll 4
    for (int l = 0; l < LCDIM; l++) mx = fmaxf(mx, col[(long)l * LEDIM] + negs[l]);
    float sm = 0.f;
#pragma unroll 4
    for (int l = 0; l < LCDIM; l++) sm += __expf(col[(long)l * LEDIM] + negs[l] - mx);
    float inv = 1.f / sm;

    float* out = beta + (long)b * LCDIM * LEDIM + e;
#pragma unroll 4
    for (int l = 0; l < LCDIM; l++)
        out[(long)l * LEDIM] = __expf(col[(long)l * LEDIM] + negs[l] - mx) * inv;
}

// ---------------- segment-sum over L into 4 partials per batch --------------
__global__ __launch_bounds__(256) void reduce_kernel(const float* __restrict__ tmp,
                                                     float* __restrict__ part, int Lvar)
{
    int b = blockIdx.x, s = blockIdx.y, n = threadIdx.x;
    int chunk = Lvar / 4;
    const float* p = tmp + ((long)b * Lvar + (long)s * chunk) * DDIM + n;
    float acc = 0.f;
#pragma unroll 8
    for (int l = 0; l < chunk; l++) acc += p[(long)l * DDIM];
    part[(b * 4 + s) * DDIM + n] = acc;
}

// ---------------- final MLP: out = relu(m@Wm+bm)@Wo+bo, one block per b -----
__global__ __launch_bounds__(512) void final_kernel(
    const float* __restrict__ r1p, const float* __restrict__ r2p,
    const float* __restrict__ Wm, const float* __restrict__ bm,
    const float* __restrict__ Wo, const float* __restrict__ bo,
    float* __restrict__ out)
{
    int b = blockIdx.x;
    int t = threadIdx.x;

    __shared__ float ms[4 * DDIM]; // m = [r1, r2, r1*r2, r1-r2]
    __shared__ float hs[MMDIM];

    if (t < DDIM) {
        float r1 = 0.f, r2 = 0.f;
#pragma unroll
        for (int s = 0; s < 4; s++) {
            r1 += r1p[(b * 4 + s) * DDIM + t];
            r2 += r2p[(b * 4 + s) * DDIM + t];
        }
        ms[t] = r1;
        ms[DDIM + t] = r2;
        ms[2 * DDIM + t] = r1 * r2;
        ms[3 * DDIM + t] = r1 - r2;
    }
    __syncthreads();

    float acc = bm[t];
#pragma unroll 8
    for (int k = 0; k < 4 * DDIM; k++) acc += ms[k] * Wm[(long)k * MMDIM + t];
    hs[t] = fmaxf(acc, 0.f);
    __syncthreads();

    int w = t >> 5, lane = t & 31;
    if (w < 3) {
        float s = 0.f;
        for (int j = lane; j < MMDIM; j += 32) s += hs[j] * Wo[j * 3 + w];
#pragma unroll
        for (int off = 16; off; off >>= 1) s += __shfl_down_sync(0xffffffffu, s, off);
        if (lane == 0) out[b * 3 + w] = s + bo[w];
    }
}

// ---------------- launch ----------------------------------------------------
extern "C" void kernel_launch(void* const* d_in, const int* in_sizes, int n_in,
                              void* d_out, int out_size)
{
    const float *criteria, *ehr, *Wa, *ba, *Wr, *br, *Wm, *bm, *Wo, *bo;
    const int *cmask, *emask;

    // Detect input ordering: setup_inputs dict order puts criteria_mask (32768)
    // at index 2; reference-arg order puts Wa (65536) there.
    if (in_sizes[2] == BB * LCDIM) {
        criteria = (const float*)d_in[0]; ehr = (const float*)d_in[1];
        cmask = (const int*)d_in[2]; emask = (const int*)d_in[3];
        Wa = (const float*)d_in[4]; ba = (const float*)d_in[5];
        Wr = (const float*)d_in[6]; br = (const float*)d_in[7];
        Wm = (const float*)d_in[8]; bm = (const float*)d_in[9];
        Wo = (const float*)d_in[10]; bo = (const float*)d_in[11];
    } else {
        criteria = (const float*)d_in[0]; ehr = (const float*)d_in[1];
        Wa = (const float*)d_in[2]; ba = (const float*)d_in[3];
        Wr = (const float*)d_in[4]; br = (const float*)d_in[5];
        Wm = (const float*)d_in[6]; bm = (const float*)d_in[7];
        Wo = (const float*)d_in[8]; bo = (const float*)d_in[9];
        cmask = (const int*)d_in[10]; emask = (const int*)d_in[11];
    }

    float *c, *e, *al, *be, *attc, *atte, *r1p, *r2p;
    cudaGetSymbolAddress((void**)&c,    g_c);
    cudaGetSymbolAddress((void**)&e,    g_e);
    cudaGetSymbolAddress((void**)&al,   g_align);
    cudaGetSymbolAddress((void**)&be,   g_beta);
    cudaGetSymbolAddress((void**)&attc, g_attc);
    cudaGetSymbolAddress((void**)&atte, g_atte);
    cudaGetSymbolAddress((void**)&r1p,  g_r1p);
    cudaGetSymbolAddress((void**)&r2p,  g_r2p);

    const long LCD = (long)LCDIM * DDIM;   // 65536
    const long LED = (long)LEDIM * DDIM;   // 262144
    const long LCE = (long)LCDIM * LEDIM;  // 262144

    // c = relu(criteria @ Wa + ba)   [32768,256]x[256,256]
    gemm_k<<<dim3(DDIM / BN, (BB * LCDIM) / BM, 1), 256>>>(
        criteria, Wa, ba, c, BB * LCDIM, DDIM, DDIM,
        DDIM, 1, 0,  DDIM, 1, 0,  0, 0, 1);

    // e = relu(ehr @ Wa + ba)        [131072,256]x[256,256]
    gemm_k<<<dim3(DDIM / BN, (BB * LEDIM) / BM, 1), 256>>>(
        ehr, Wa, ba, e, BB * LEDIM, DDIM, DDIM,
        DDIM, 1, 0,  DDIM, 1, 0,  0, 0, 1);

    // align[b] = c[b] @ e[b]^T       batched [256,256]x[256,1024]
    gemm_k<<<dim3(LEDIM / BN, LCDIM / BM, BB), 256>>>(
        c, e, nullptr, al, LCDIM, LEDIM, DDIM,
        DDIM, 1, LCD,  1, DDIM, LED,  LCE, 0, 0);

    // beta = colsoftmax(align + cmask)  (must run before alpha overwrites align)
    beta_kernel<<<BB * (LEDIM / 256), 256>>>(al, be, cmask);

    // alpha = rowsoftmax(align + emask), in place
    alpha_kernel<<<BB * LCDIM, 256>>>(al, emask);

    // att_c[b] = alpha[b] @ ehr[b]   batched [256,1024]x[1024,256]
    gemm_k<<<dim3(DDIM / BN, LCDIM / BM, BB), 256>>>(
        al, ehr, nullptr, attc, LCDIM, DDIM, LEDIM,
        LEDIM, 1, LCE,  DDIM, 1, LED,  LCD, 0, 0);

    // att_e[b] = beta[b]^T @ criteria[b]  batched [1024,256]x[256,256]
    gemm_k<<<dim3(DDIM / BN, LEDIM / BM, BB), 256>>>(
        be, criteria, nullptr, atte, LEDIM, DDIM, LCDIM,
        1, LEDIM, LCE,  DDIM, 1, LCD,  LED, 0, 0);

    // tmp1 (reuse g_c) = relu(att_c @ Wr[0:256] + criteria @ Wr[256:512] + br)
    gemm_k<<<dim3(DDIM / BN, (BB * LCDIM) / BM, 1), 256>>>(
        attc, Wr, nullptr, c, BB * LCDIM, DDIM, DDIM,
        DDIM, 1, 0,  DDIM, 1, 0,  0, 0, 0);
    gemm_k<<<dim3(DDIM / BN, (BB * LCDIM) / BM, 1), 256>>>(
        criteria, Wr + DDIM * DDIM, br, c, BB * LCDIM, DDIM, DDIM,
        DDIM, 1, 0,  DDIM, 1, 0,  0, 1, 1);

    // tmp2 (reuse g_e) = relu(att_e @ Wr[0:256] + ehr @ Wr[256:512] + br)
    gemm_k<<<dim3(DDIM / BN, (BB * LEDIM) / BM, 1), 256>>>(
        atte, Wr, nullptr, e, BB * LEDIM, DDIM, DDIM,
        DDIM, 1, 0,  DDIM, 1, 0,  0, 0, 0);
    gemm_k<<<dim3(DDIM / BN, (BB * LEDIM) / BM, 1), 256>>>(
        ehr, Wr + DDIM * DDIM, br, e, BB * LEDIM, DDIM, DDIM,
        DDIM, 1, 0,  DDIM, 1, 0,  0, 1, 1);

    // r1/r2 partial sums over L
    reduce_kernel<<<dim3(BB, 4), 256>>>(c, r1p, LCDIM);
    reduce_kernel<<<dim3(BB, 4), 256>>>(e, r2p, LEDIM);

    // final head
    final_kernel<<<BB, 512>>>(r1p, r2p, Wm, bm, Wo, bo, (float*)d_out);
}

// round 2
// speedup vs baseline: 1.7623x; 1.7623x over previous
#include <cuda_runtime.h>
#include <cstdint>

#define BB 128
#define LCDIM 256
#define LEDIM 1024
#define DDIM 256
#define MMDIM 512
#define NEGV -1e9f

// ---------------- scratch ----------------------------------------------------
__device__ float g_c[(size_t)BB * LCDIM * DDIM];      // c, later r1-pre
__device__ float g_e[(size_t)BB * LEDIM * DDIM];      // e, later r2-pre
__device__ float g_align[(size_t)BB * LCDIM * LEDIM]; // align, then alpha in-place
__device__ float g_beta[(size_t)BB * LCDIM * LEDIM];
__device__ float g_attc[(size_t)BB * LCDIM * DDIM];
__device__ float g_atte[(size_t)BB * LEDIM * DDIM];
__device__ float g_r1p[BB * 4 * DDIM];
__device__ float g_r2p[BB * 4 * DDIM];
__device__ float g_cmx[BB * LEDIM];
__device__ float g_cinv[BB * LEDIM];

// ---------------- tf32 helpers ----------------------------------------------
__device__ __forceinline__ uint32_t tf32bits(float x) {
    uint32_t u;
    asm("cvt.rna.tf32.f32 %0, %1;" : "=r"(u) : "f"(x));
    return u;
}

__device__ __forceinline__ void ldsm4(uint32_t& r0, uint32_t& r1, uint32_t& r2,
                                      uint32_t& r3, const uint32_t* p) {
    uint32_t addr = (uint32_t)__cvta_generic_to_shared(p);
    asm volatile("ldmatrix.sync.aligned.m8n8.x4.shared.b16 {%0,%1,%2,%3}, [%4];"
                 : "=r"(r0), "=r"(r1), "=r"(r2), "=r"(r3) : "r"(addr));
}

__device__ __forceinline__ void mma8(float* c, const uint32_t* a, uint32_t b0, uint32_t b1) {
    asm volatile(
        "mma.sync.aligned.m16n8k8.row.col.f32.tf32.tf32.f32 "
        "{%0,%1,%2,%3}, {%4,%5,%6,%7}, {%8,%9}, {%0,%1,%2,%3};"
        : "+f"(c[0]), "+f"(c[1]), "+f"(c[2]), "+f"(c[3])
        : "r"(a[0]), "r"(a[1]), "r"(a[2]), "r"(a[3]), "r"(b0), "r"(b1));
}

// ---------------- TF32 tensor-core strided batched GEMM ----------------------
// C[M,N] row-major = epilogue(A@B). A[m*sAm+k*sAk], B[k*sBk+n*sBn].
// Optional A2: rows of A beyond k=Ksplit come from A2 (same strides) — fused
// concat GEMM. M,N multiples of 128; K multiple of 16.
#define BM 128
#define BN 128
#define BKT 16
#define PAD 20

__global__ __launch_bounds__(256) void gemm_tc(
    const float* __restrict__ A, const float* __restrict__ A2, int Ksplit,
    const float* __restrict__ B, const float* __restrict__ bias,
    float* __restrict__ C,
    int M, int N, int K,
    long sAm, long sAk, long bsA,
    long sBk, long sBn, long bsB,
    long bsC, int do_relu)
{
    A += (long)blockIdx.z * bsA;
    B += (long)blockIdx.z * bsB;
    C += (long)blockIdx.z * bsC;

    __shared__ uint32_t As[BM * PAD];
    __shared__ uint32_t Bs[BN * PAD];

    const int tid = threadIdx.x;
    const int lane = tid & 31;
    const int w = tid >> 5;
    const int wm = (w & 1) * 64;
    const int wn = (w >> 1) * 32;
    const int m0 = blockIdx.y * BM;
    const int n0 = blockIdx.x * BN;

    float acc[4][4][4];
#pragma unroll
    for (int i = 0; i < 4; i++)
#pragma unroll
        for (int j = 0; j < 4; j++)
#pragma unroll
            for (int r = 0; r < 4; r++) acc[i][j][r] = 0.f;

    for (int k0 = 0; k0 < K; k0 += BKT) {
        const float* Ap = A;
        int kb = k0;
        if (A2 && k0 >= Ksplit) { Ap = A2; kb = k0 - Ksplit; }

        // A tile -> As[m][k] (tf32 bits)
#pragma unroll
        for (int i = 0; i < 8; i++) {
            int idx = tid + i * 256;
            int m, k;
            if (sAk == 1) { k = idx & 15; m = idx >> 4; }
            else          { m = idx & 127; k = idx >> 7; }
            float v = Ap[(long)(m0 + m) * sAm + (long)(kb + k) * sAk];
            As[m * PAD + k] = tf32bits(v);
        }
        // B tile -> Bs[n][k] (tf32 bits)
#pragma unroll
        for (int i = 0; i < 8; i++) {
            int idx = tid + i * 256;
            int n, k;
            if (sBn == 1) { n = idx & 127; k = idx >> 7; }
            else          { k = idx & 15; n = idx >> 4; }
            float v = B[(long)(k0 + k) * sBk + (long)(n0 + n) * sBn];
            Bs[n * PAD + k] = tf32bits(v);
        }
        __syncthreads();

#pragma unroll
        for (int kk = 0; kk < 2; kk++) {
            const int ks = kk * 8;
            uint32_t a[4][4], bfr[2][4];

            const int arow = (lane < 16 ? lane : lane - 16);
            const int acol = ks + (lane < 16 ? 0 : 4);
#pragma unroll
            for (int mt = 0; mt < 4; mt++)
                ldsm4(a[mt][0], a[mt][1], a[mt][2], a[mt][3],
                      &As[(wm + mt * 16 + arow) * PAD + acol]);

            const int brow = (lane & 7) + (lane >= 16 ? 8 : 0);
            const int bcol = ks + ((lane & 8) ? 4 : 0);
#pragma unroll
            for (int np = 0; np < 2; np++)
                ldsm4(bfr[np][0], bfr[np][1], bfr[np][2], bfr[np][3],
                      &Bs[(wn + np * 16 + brow) * PAD + bcol]);

#pragma unroll
            for (int mt = 0; mt < 4; mt++)
#pragma unroll
                for (int nt = 0; nt < 4; nt++)
                    mma8(acc[mt][nt], a[mt],
                         bfr[nt >> 1][(nt & 1) * 2], bfr[nt >> 1][(nt & 1) * 2 + 1]);
        }
        __syncthreads();
    }

    // epilogue
    const int g = lane >> 2, tg = lane & 3;
#pragma unroll
    for (int mt = 0; mt < 4; mt++) {
#pragma unroll
        for (int nt = 0; nt < 4; nt++) {
            int row = m0 + wm + mt * 16 + g;
            int col = n0 + wn + nt * 8 + tg * 2;
            float bv0 = 0.f, bv1 = 0.f;
            if (bias) { bv0 = bias[col]; bv1 = bias[col + 1]; }
#pragma unroll
            for (int h = 0; h < 2; h++) {
                long ci = (long)(row + h * 8) * N + col;
                float v0 = acc[mt][nt][2 * h] + bv0;
                float v1 = acc[mt][nt][2 * h + 1] + bv1;
                if (do_relu) { v0 = fmaxf(v0, 0.f); v1 = fmaxf(v1, 0.f); }
                *reinterpret_cast<float2*>(C + ci) = make_float2(v0, v1);
            }
        }
    }
}

// ---------------- alpha: softmax over Le (axis=2), in-place ------------------
__global__ __launch_bounds__(256) void alpha_kernel(float* __restrict__ align,
                                                    const int* __restrict__ em)
{
    int b = blockIdx.x / LCDIM;
    long base = (long)blockIdx.x * LEDIM;
    int t = threadIdx.x;

    float v[4];
    float mx = -3.4e38f;
#pragma unroll
    for (int i = 0; i < 4; i++) {
        int e = t + i * 256;
        float x = align[base + e];
        if (em[b * LEDIM + e] == 0) x += NEGV;
        v[i] = x;
        mx = fmaxf(mx, x);
    }
    __shared__ float red[256];
    red[t] = mx; __syncthreads();
    for (int s = 128; s > 0; s >>= 1) { if (t < s) red[t] = fmaxf(red[t], red[t + s]); __syncthreads(); }
    mx = red[0]; __syncthreads();

    float sm = 0.f;
#pragma unroll
    for (int i = 0; i < 4; i++) { v[i] = __expf(v[i] - mx); sm += v[i]; }
    red[t] = sm; __syncthreads();
    for (int s = 128; s > 0; s >>= 1) { if (t < s) red[t] += red[t + s]; __syncthreads(); }
    float inv = 1.f / red[0];

#pragma unroll
    for (int i = 0; i < 4; i++) align[base + t + i * 256] = v[i] * inv;
}

// ---------------- beta: online column stats (1 read pass) --------------------
__global__ __launch_bounds__(256) void colstats_kernel(const float* __restrict__ align,
                                                       const int* __restrict__ cm,
                                                       float* __restrict__ mxo,
                                                       float* __restrict__ invo)
{
    int b = blockIdx.x / (LEDIM / 256);
    int e = (blockIdx.x % (LEDIM / 256)) * 256 + threadIdx.x;

    __shared__ float negs[LCDIM];
    for (int l = threadIdx.x; l < LCDIM; l += 256)
        negs[l] = cm[b * LCDIM + l] ? 0.f : NEGV;
    __syncthreads();

    const float* col = align + (long)b * LCDIM * LEDIM + e;
    float m = -3.4e38f, s = 0.f;
#pragma unroll 4
    for (int l = 0; l < LCDIM; l++) {
        float x = col[(long)l * LEDIM] + negs[l];
        float nm = fmaxf(m, x);
        s = s * __expf(m - nm) + __expf(x - nm);
        m = nm;
    }
    mxo[b * LEDIM + e] = m;
    invo[b * LEDIM + e] = 1.f / s;
}

// ---------------- beta write pass (row-coalesced) ----------------------------
__global__ __launch_bounds__(256) void betawrite_kernel(const float* __restrict__ align,
                                                        float* __restrict__ beta,
                                                        const int* __restrict__ cm,
                                                        const float* __restrict__ mx,
                                                        const float* __restrict__ inv)
{
    int b = blockIdx.x / LCDIM;
    int l = blockIdx.x % LCDIM;
    float neg = cm[b * LCDIM + l] ? 0.f : NEGV;
    long base = (long)blockIdx.x * LEDIM;
    const float* mxb = mx + b * LEDIM;
    const float* invb = inv + b * LEDIM;
#pragma unroll
    for (int i = 0; i < 4; i++) {
        int e = threadIdx.x + i * 256;
        beta[base + e] = __expf(align[base + e] + neg - mxb[e]) * invb[e];
    }
}

// ---------------- segment-sum over L into 4 partials per batch ---------------
__global__ __launch_bounds__(256) void reduce_kernel(const float* __restrict__ tmp,
                                                     float* __restrict__ part, int Lvar)
{
    int b = blockIdx.x, s = blockIdx.y, n = threadIdx.x;
    int chunk = Lvar / 4;
    const float* p = tmp + ((long)b * Lvar + (long)s * chunk) * DDIM + n;
    float acc = 0.f;
#pragma unroll 8
    for (int l = 0; l < chunk; l++) acc += p[(long)l * DDIM];
    part[(b * 4 + s) * DDIM + n] = acc;
}

// ---------------- final MLP --------------------------------------------------
__global__ __launch_bounds__(512) void final_kernel(
    const float* __restrict__ r1p, const float* __restrict__ r2p,
    const float* __restrict__ Wm, const float* __restrict__ bm,
    const float* __restrict__ Wo, const float* __restrict__ bo,
    float* __restrict__ out)
{
    int b = blockIdx.x;
    int t = threadIdx.x;

    __shared__ float ms[4 * DDIM];
    __shared__ float hs[MMDIM];

    if (t < DDIM) {
        float r1 = 0.f, r2 = 0.f;
#pragma unroll
        for (int s = 0; s < 4; s++) {
            r1 += r1p[(b * 4 + s) * DDIM + t];
            r2 += r2p[(b * 4 + s) * DDIM + t];
        }
        ms[t] = r1;
        ms[DDIM + t] = r2;
        ms[2 * DDIM + t] = r1 * r2;
        ms[3 * DDIM + t] = r1 - r2;
    }
    __syncthreads();

    float acc = bm[t];
#pragma unroll 8
    for (int k = 0; k < 4 * DDIM; k++) acc += ms[k] * Wm[(long)k * MMDIM + t];
    hs[t] = fmaxf(acc, 0.f);
    __syncthreads();

    int w = t >> 5, lane = t & 31;
    if (w < 3) {
        float s = 0.f;
        for (int j = lane; j < MMDIM; j += 32) s += hs[j] * Wo[j * 3 + w];
#pragma unroll
        for (int off = 16; off; off >>= 1) s += __shfl_down_sync(0xffffffffu, s, off);
        if (lane == 0) out[b * 3 + w] = s + bo[w];
    }
}

// ---------------- launch -----------------------------------------------------
extern "C" void kernel_launch(void* const* d_in, const int* in_sizes, int n_in,
                              void* d_out, int out_size)
{
    const float *criteria, *ehr, *Wa, *ba, *Wr, *br, *Wm, *bm, *Wo, *bo;
    const int *cmask, *emask;

    if (in_sizes[2] == BB * LCDIM) {
        criteria = (const float*)d_in[0]; ehr = (const float*)d_in[1];
        cmask = (const int*)d_in[2]; emask = (const int*)d_in[3];
        Wa = (const float*)d_in[4]; ba = (const float*)d_in[5];
        Wr = (const float*)d_in[6]; br = (const float*)d_in[7];
        Wm = (const float*)d_in[8]; bm = (const float*)d_in[9];
        Wo = (const float*)d_in[10]; bo = (const float*)d_in[11];
    } else {
        criteria = (const float*)d_in[0]; ehr = (const float*)d_in[1];
        Wa = (const float*)d_in[2]; ba = (const float*)d_in[3];
        Wr = (const float*)d_in[4]; br = (const float*)d_in[5];
        Wm = (const float*)d_in[6]; bm = (const float*)d_in[7];
        Wo = (const float*)d_in[8]; bo = (const float*)d_in[9];
        cmask = (const int*)d_in[10]; emask = (const int*)d_in[11];
    }

    float *c, *e, *al, *be, *attc, *atte, *r1p, *r2p, *cmx, *cinv;
    cudaGetSymbolAddress((void**)&c,    g_c);
    cudaGetSymbolAddress((void**)&e,    g_e);
    cudaGetSymbolAddress((void**)&al,   g_align);
    cudaGetSymbolAddress((void**)&be,   g_beta);
    cudaGetSymbolAddress((void**)&attc, g_attc);
    cudaGetSymbolAddress((void**)&atte, g_atte);
    cudaGetSymbolAddress((void**)&r1p,  g_r1p);
    cudaGetSymbolAddress((void**)&r2p,  g_r2p);
    cudaGetSymbolAddress((void**)&cmx,  g_cmx);
    cudaGetSymbolAddress((void**)&cinv, g_cinv);

    const long LCD = (long)LCDIM * DDIM;   // 65536
    const long LED = (long)LEDIM * DDIM;   // 262144
    const long LCE = (long)LCDIM * LEDIM;  // 262144

    // c = relu(criteria @ Wa + ba)
    gemm_tc<<<dim3(DDIM / BN, (BB * LCDIM) / BM, 1), 256>>>(
        criteria, nullptr, 0, Wa, ba, c, BB * LCDIM, DDIM, DDIM,
        DDIM, 1, 0,  DDIM, 1, 0,  0, 1);

    // e = relu(ehr @ Wa + ba)
    gemm_tc<<<dim3(DDIM / BN, (BB * LEDIM) / BM, 1), 256>>>(
        ehr, nullptr, 0, Wa, ba, e, BB * LEDIM, DDIM, DDIM,
        DDIM, 1, 0,  DDIM, 1, 0,  0, 1);

    // align[b] = c[b] @ e[b]^T
    gemm_tc<<<dim3(LEDIM / BN, LCDIM / BM, BB), 256>>>(
        c, nullptr, 0, e, nullptr, al, LCDIM, LEDIM, DDIM,
        DDIM, 1, LCD,  1, DDIM, LED,  LCE, 0);

    // beta stats + write (before alpha clobbers align)
    colstats_kernel<<<BB * (LEDIM / 256), 256>>>(al, cmask, cmx, cinv);
    betawrite_kernel<<<BB * LCDIM, 256>>>(al, be, cmask, cmx, cinv);

    // alpha in-place
    alpha_kernel<<<BB * LCDIM, 256>>>(al, emask);

    // att_c[b] = alpha[b] @ ehr[b]
    gemm_tc<<<dim3(DDIM / BN, LCDIM / BM, BB), 256>>>(
        al, nullptr, 0, ehr, nullptr, attc, LCDIM, DDIM, LEDIM,
        LEDIM, 1, LCE,  DDIM, 1, LED,  LCD, 0);

    // att_e[b] = beta[b]^T @ criteria[b]
    gemm_tc<<<dim3(DDIM / BN, LEDIM / BM, BB), 256>>>(
        be, nullptr, 0, criteria, nullptr, atte, LEDIM, DDIM, LCDIM,
        1, LEDIM, LCE,  DDIM, 1, LCD,  LED, 0);

    // r1-pre (reuse g_c) = relu([attc, criteria] @ Wr + br), K=512 fused concat
    gemm_tc<<<dim3(DDIM / BN, (BB * LCDIM) / BM, 1), 256>>>(
        attc, criteria, DDIM, Wr, br, c, BB * LCDIM, DDIM, 2 * DDIM,
        DDIM, 1, 0,  DDIM, 1, 0,  0, 1);

    // r2-pre (reuse g_e) = relu([atte, ehr] @ Wr + br)
    gemm_tc<<<dim3(DDIM / BN, (BB * LEDIM) / BM, 1), 256>>>(
        atte, ehr, DDIM, Wr, br, e, BB * LEDIM, DDIM, 2 * DDIM,
        DDIM, 1, 0,  DDIM, 1, 0,  0, 1);

    // r1/r2 partial sums
    reduce_kernel<<<dim3(BB, 4), 256>>>(c, r1p, LCDIM);
    reduce_kernel<<<dim3(BB, 4), 256>>>(e, r2p, LEDIM);

    final_kernel<<<BB, 512>>>(r1p, r2p, Wm, bm, Wo, bo, (float*)d_out);
}

// round 4
// speedup vs baseline: 3.2568x; 1.8480x over previous
#include <cuda_runtime.h>
#include <cstdint>

#define BB 128
#define LCDIM 256
#define LEDIM 1024
#define DDIM 256
#define MMDIM 512
#define NEGV -1e9f

// ---------------- scratch ----------------------------------------------------
__device__ float g_c[(size_t)BB * LCDIM * DDIM];      // c, later r1-pre
__device__ float g_e[(size_t)BB * LEDIM * DDIM];      // e, later r2-pre
__device__ float g_align[(size_t)BB * LCDIM * LEDIM]; // align, then alpha in-place
__device__ float g_betaT[(size_t)BB * LCDIM * LEDIM]; // beta^T (Le, Lc) per batch
__device__ float g_attc[(size_t)BB * LCDIM * DDIM];
__device__ float g_atte[(size_t)BB * LEDIM * DDIM];
__device__ float g_ehrT[(size_t)BB * LEDIM * DDIM];   // (D, Le) per batch
__device__ float g_critT[(size_t)BB * LCDIM * DDIM];  // (D, Lc) per batch
__device__ float g_WaT[DDIM * DDIM];
__device__ float g_WrT[2 * DDIM * DDIM];
__device__ float g_r1p[BB * 4 * DDIM];
__device__ float g_r2p[BB * 4 * DDIM];
__device__ float g_cmx[BB * LEDIM];
__device__ float g_cinv[BB * LEDIM];

// ---------------- mma helpers ------------------------------------------------
__device__ __forceinline__ uint32_t tf32rna(float x) {
    uint32_t u;
    asm("cvt.rna.tf32.f32 %0, %1;" : "=r"(u) : "f"(x));
    return u;
}

__device__ __forceinline__ void ldsm4(uint32_t& r0, uint32_t& r1, uint32_t& r2,
                                      uint32_t& r3, const uint32_t* p) {
    uint32_t addr = (uint32_t)__cvta_generic_to_shared(p);
    asm volatile("ldmatrix.sync.aligned.m8n8.x4.shared.b16 {%0,%1,%2,%3}, [%4];"
                 : "=r"(r0), "=r"(r1), "=r"(r2), "=r"(r3) : "r"(addr));
}

__device__ __forceinline__ void mma8(float* c, const uint32_t* a, uint32_t b0, uint32_t b1) {
    asm volatile(
        "mma.sync.aligned.m16n8k8.row.col.f32.tf32.tf32.f32 "
        "{%0,%1,%2,%3}, {%4,%5,%6,%7}, {%8,%9}, {%0,%1,%2,%3};"
        : "+f"(c[0]), "+f"(c[1]), "+f"(c[2]), "+f"(c[3])
        : "r"(a[0]), "r"(a[1]), "r"(a[2]), "r"(a[3]), "r"(b0), "r"(b1));
}

// ---------------- TF32 tensor-core GEMM, all operands k-contiguous -----------
// C[M,N] row-major = epilogue(A@B). A[m][k] at A + m*sAm + k (sAk==1).
// B logical [k][n] stored n-major: element at B + n*sBn + k (sBk==1).
// Optional A2: k >= Ksplit comes from A2 (fused concat).
// Conversion to tf32 happens with cvt.rna at SMEM-staging time (round-to-
// nearest; raw-bit truncation was 2x over the error budget).
#define BM 128
#define BN 128
#define BKT 16
#define PAD 20

__global__ __launch_bounds__(256) void gemm_tc(
    const float* __restrict__ A, const float* __restrict__ A2, int Ksplit,
    const float* __restrict__ B, const float* __restrict__ bias,
    float* __restrict__ C,
    int M, int N, int K,
    long sAm, long bsA, long sBn, long bsB, long bsC, int do_relu)
{
    A += (long)blockIdx.z * bsA;
    if (A2) A2 += (long)blockIdx.z * bsA;
    B += (long)blockIdx.z * bsB;
    C += (long)blockIdx.z * bsC;

    __shared__ uint32_t As[2][BM * PAD];
    __shared__ uint32_t Bs[2][BN * PAD];

    const int tid = threadIdx.x;
    const int lane = tid & 31;
    const int w = tid >> 5;
    const int wm = (w & 1) * 64;
    const int wn = (w >> 1) * 32;
    const int m0 = blockIdx.y * BM;
    const int n0 = blockIdx.x * BN;

    // loader mapping: 512 float4 per operand tile, 2 per thread
    const int lrow0 = tid >> 2;              // 0..63
    const int lk = (tid & 3) * 4;            // 0,4,8,12

    float4 ra[2], rb[2];

    auto loadA = [&](int k0) {
        const float* Ap = A; int kb = k0;
        if (A2 && k0 >= Ksplit) { Ap = A2; kb = k0 - Ksplit; }
#pragma unroll
        for (int i = 0; i < 2; i++) {
            int m = lrow0 + i * 64;
            ra[i] = *reinterpret_cast<const float4*>(Ap + (long)(m0 + m) * sAm + kb + lk);
        }
    };
    auto loadB = [&](int k0) {
#pragma unroll
        for (int i = 0; i < 2; i++) {
            int n = lrow0 + i * 64;
            rb[i] = *reinterpret_cast<const float4*>(B + (long)(n0 + n) * sBn + k0 + lk);
        }
    };
    auto stage = [&](int s) {
#pragma unroll
        for (int i = 0; i < 2; i++) {
            int r = lrow0 + i * 64;
            uint4 ua = make_uint4(tf32rna(ra[i].x), tf32rna(ra[i].y),
                                  tf32rna(ra[i].z), tf32rna(ra[i].w));
            uint4 ub = make_uint4(tf32rna(rb[i].x), tf32rna(rb[i].y),
                                  tf32rna(rb[i].z), tf32rna(rb[i].w));
            *reinterpret_cast<uint4*>(&As[s][r * PAD + lk]) = ua;
            *reinterpret_cast<uint4*>(&Bs[s][r * PAD + lk]) = ub;
        }
    };

    float acc[4][4][4];
#pragma unroll
    for (int i = 0; i < 4; i++)
#pragma unroll
        for (int j = 0; j < 4; j++)
#pragma unroll
            for (int r = 0; r < 4; r++) acc[i][j][r] = 0.f;

    loadA(0); loadB(0);
    stage(0);
    __syncthreads();

    const int T = K / BKT;
    for (int t = 0; t < T; t++) {
        if (t + 1 < T) { loadA((t + 1) * BKT); loadB((t + 1) * BKT); }
        const int s = t & 1;

#pragma unroll
        for (int kk = 0; kk < 2; kk++) {
            const int ks = kk * 8;
            uint32_t a[4][4], bfr[2][4];

            const int arow = (lane < 16 ? lane : lane - 16);
            const int acol = ks + (lane < 16 ? 0 : 4);
#pragma unroll
            for (int mt = 0; mt < 4; mt++)
                ldsm4(a[mt][0], a[mt][1], a[mt][2], a[mt][3],
                      &As[s][(wm + mt * 16 + arow) * PAD + acol]);

            const int brow = (lane & 7) + (lane >= 16 ? 8 : 0);
            const int bcol = ks + ((lane & 8) ? 4 : 0);
#pragma unroll
            for (int np = 0; np < 2; np++)
                ldsm4(bfr[np][0], bfr[np][1], bfr[np][2], bfr[np][3],
                      &Bs[s][(wn + np * 16 + brow) * PAD + bcol]);

#pragma unroll
            for (int mt = 0; mt < 4; mt++)
#pragma unroll
                for (int nt = 0; nt < 4; nt++)
                    mma8(acc[mt][nt], a[mt],
                         bfr[nt >> 1][(nt & 1) * 2], bfr[nt >> 1][(nt & 1) * 2 + 1]);
        }

        if (t + 1 < T) {
            stage(s ^ 1);
            __syncthreads();
        }
    }

    // epilogue
    const int g = lane >> 2, tg = lane & 3;
#pragma unroll
    for (int mt = 0; mt < 4; mt++) {
#pragma unroll
        for (int nt = 0; nt < 4; nt++) {
            int row = m0 + wm + mt * 16 + g;
            int col = n0 + wn + nt * 8 + tg * 2;
            float bv0 = 0.f, bv1 = 0.f;
            if (bias) { bv0 = bias[col]; bv1 = bias[col + 1]; }
#pragma unroll
            for (int h = 0; h < 2; h++) {
                long ci = (long)(row + h * 8) * N + col;
                float v0 = acc[mt][nt][2 * h] + bv0;
                float v1 = acc[mt][nt][2 * h + 1] + bv1;
                if (do_relu) { v0 = fmaxf(v0, 0.f); v1 = fmaxf(v1, 0.f); }
                *reinterpret_cast<float2*>(C + ci) = make_float2(v0, v1);
            }
        }
    }
}

// ---------------- tiled transpose: in (R,C) -> out (C,R), batched ------------
__global__ __launch_bounds__(256) void transpose_k(const float* __restrict__ in,
                                                   float* __restrict__ out,
                                                   int R, int C, long ibs, long obs)
{
    __shared__ float tile[32][33];
    in += (long)blockIdx.z * ibs;
    out += (long)blockIdx.z * obs;
    int c0 = blockIdx.x * 32, r0 = blockIdx.y * 32;
#pragma unroll
    for (int j = 0; j < 32; j += 8)
        tile[threadIdx.y + j][threadIdx.x] =
            in[(long)(r0 + threadIdx.y + j) * C + c0 + threadIdx.x];
    __syncthreads();
#pragma unroll
    for (int j = 0; j < 32; j += 8)
        out[(long)(c0 + threadIdx.y + j) * R + r0 + threadIdx.x] =
            tile[threadIdx.x][threadIdx.y + j];
}

// ---------------- alpha: softmax over Le (axis=2), in-place ------------------
__global__ __launch_bounds__(256) void alpha_kernel(float* __restrict__ align,
                                                    const int* __restrict__ em)
{
    int b = blockIdx.x / LCDIM;
    long base = (long)blockIdx.x * LEDIM;
    int t = threadIdx.x;

    float v[4];
    float mx = -3.4e38f;
#pragma unroll
    for (int i = 0; i < 4; i++) {
        int e = t + i * 256;
        float x = align[base + e];
        if (em[b * LEDIM + e] == 0) x += NEGV;
        v[i] = x;
        mx = fmaxf(mx, x);
    }
    __shared__ float red[256];
    red[t] = mx; __syncthreads();
    for (int s = 128; s > 0; s >>= 1) { if (t < s) red[t] = fmaxf(red[t], red[t + s]); __syncthreads(); }
    mx = red[0]; __syncthreads();

    float sm = 0.f;
#pragma unroll
    for (int i = 0; i < 4; i++) { v[i] = __expf(v[i] - mx); sm += v[i]; }
    red[t] = sm; __syncthreads();
    for (int s = 128; s > 0; s >>= 1) { if (t < s) red[t] += red[t + s]; __syncthreads(); }
    float inv = 1.f / red[0];

#pragma unroll
    for (int i = 0; i < 4; i++) align[base + t + i * 256] = v[i] * inv;
}

// ---------------- beta: online column stats (1 read pass) --------------------
__global__ __launch_bounds__(256) void colstats_kernel(const float* __restrict__ align,
                                                       const int* __restrict__ cm,
                                                       float* __restrict__ mxo,
                                                       float* __restrict__ invo)
{
    int b = blockIdx.x / (LEDIM / 256);
    int e = (blockIdx.x % (LEDIM / 256)) * 256 + threadIdx.x;

    __shared__ float negs[LCDIM];
    for (int l = threadIdx.x; l < LCDIM; l += 256)
        negs[l] = cm[b * LCDIM + l] ? 0.f : NEGV;
    __syncthreads();

    const float* col = align + (long)b * LCDIM * LEDIM + e;
    float m = -3.4e38f, s = 0.f;
#pragma unroll 4
    for (int l = 0; l < LCDIM; l++) {
        float x = col[(long)l * LEDIM] + negs[l];
        float nm = fmaxf(m, x);
        s = s * __expf(m - nm) + __expf(x - nm);
        m = nm;
    }
    mxo[b * LEDIM + e] = m;
    invo[b * LEDIM + e] = 1.f / s;
}

// ---------------- beta write: fused softmax-normalize + transpose ------------
__global__ void betaT_kernel(const float* __restrict__ align,
                             float* __restrict__ betaT,
                             const int* __restrict__ cm,
                             const float* __restrict__ mx,
                             const float* __restrict__ inv)
{
    int b = blockIdx.z;
    int e0 = blockIdx.x * 32, l0 = blockIdx.y * 32;
    __shared__ float tile[32][33];
    const float* al = align + (long)b * LCDIM * LEDIM;
#pragma unroll
    for (int j = 0; j < 32; j += 8) {
        int l = l0 + threadIdx.y + j, e = e0 + threadIdx.x;
        float neg = cm[b * LCDIM + l] ? 0.f : NEGV;
        tile[threadIdx.y + j][threadIdx.x] =
            __expf(al[(long)l * LEDIM + e] + neg - mx[b * LEDIM + e]) * inv[b * LEDIM + e];
    }
    __syncthreads();
    float* out = betaT + (long)b * LCDIM * LEDIM;
#pragma unroll
    for (int j = 0; j < 32; j += 8)
        out[(long)(e0 + threadIdx.y + j) * LCDIM + l0 + threadIdx.x] =
            tile[threadIdx.x][threadIdx.y + j];
}

// ---------------- segment-sum over L into 4 partials per batch ---------------
__global__ __launch_bounds__(256) void reduce_kernel(const float* __restrict__ tmp,
                                                     float* __restrict__ part, int Lvar)
{
    int b = blockIdx.x, s = blockIdx.y, n = threadIdx.x;
    int chunk = Lvar / 4;
    const float* p = tmp + ((long)b * Lvar + (long)s * chunk) * DDIM + n;
    float acc = 0.f;
#pragma unroll 8
    for (int l = 0; l < chunk; l++) acc += p[(long)l * DDIM];
    part[(b * 4 + s) * DDIM + n] = acc;
}

// ---------------- final MLP --------------------------------------------------
__global__ __launch_bounds__(512) void final_kernel(
    const float* __restrict__ r1p, const float* __restrict__ r2p,
    const float* __restrict__ Wm, const float* __restrict__ bm,
    const float* __restrict__ Wo, const float* __restrict__ bo,
    float* __restrict__ out)
{
    int b = blockIdx.x;
    int t = threadIdx.x;

    __shared__ float ms[4 * DDIM];
    __shared__ float hs[MMDIM];

    if (t < DDIM) {
        float r1 = 0.f, r2 = 0.f;
#pragma unroll
        for (int s = 0; s < 4; s++) {
            r1 += r1p[(b * 4 + s) * DDIM + t];
            r2 += r2p[(b * 4 + s) * DDIM + t];
        }
        ms[t] = r1;
        ms[DDIM + t] = r2;
        ms[2 * DDIM + t] = r1 * r2;
        ms[3 * DDIM + t] = r1 - r2;
    }
    __syncthreads();

    float acc = bm[t];
#pragma unroll 8
    for (int k = 0; k < 4 * DDIM; k++) acc += ms[k] * Wm[(long)k * MMDIM + t];
    hs[t] = fmaxf(acc, 0.f);
    __syncthreads();

    int w = t >> 5, lane = t & 31;
    if (w < 3) {
        float s = 0.f;
        for (int j = lane; j < MMDIM; j += 32) s += hs[j] * Wo[j * 3 + w];
#pragma unroll
        for (int off = 16; off; off >>= 1) s += __shfl_down_sync(0xffffffffu, s, off);
        if (lane == 0) out[b * 3 + w] = s + bo[w];
    }
}

// ---------------- launch -----------------------------------------------------
extern "C" void kernel_launch(void* const* d_in, const int* in_sizes, int n_in,
                              void* d_out, int out_size)
{
    const float *criteria, *ehr, *Wa, *ba, *Wr, *br, *Wm, *bm, *Wo, *bo;
    const int *cmask, *emask;

    if (in_sizes[2] == BB * LCDIM) {
        criteria = (const float*)d_in[0]; ehr = (const float*)d_in[1];
        cmask = (const int*)d_in[2]; emask = (const int*)d_in[3];
        Wa = (const float*)d_in[4]; ba = (const float*)d_in[5];
        Wr = (const float*)d_in[6]; br = (const float*)d_in[7];
        Wm = (const float*)d_in[8]; bm = (const float*)d_in[9];
        Wo = (const float*)d_in[10]; bo = (const float*)d_in[11];
    } else {
        criteria = (const float*)d_in[0]; ehr = (const float*)d_in[1];
        Wa = (const float*)d_in[2]; ba = (const float*)d_in[3];
        Wr = (const float*)d_in[4]; br = (const float*)d_in[5];
        Wm = (const float*)d_in[6]; bm = (const float*)d_in[7];
        Wo = (const float*)d_in[8]; bo = (const float*)d_in[9];
        cmask = (const int*)d_in[10]; emask = (const int*)d_in[11];
    }

    float *c, *e, *al, *beT, *attc, *atte, *ehrT, *critT, *WaT, *WrT;
    float *r1p, *r2p, *cmx, *cinv;
    cudaGetSymbolAddress((void**)&c,     g_c);
    cudaGetSymbolAddress((void**)&e,     g_e);
    cudaGetSymbolAddress((void**)&al,    g_align);
    cudaGetSymbolAddress((void**)&beT,   g_betaT);
    cudaGetSymbolAddress((void**)&attc,  g_attc);
    cudaGetSymbolAddress((void**)&atte,  g_atte);
    cudaGetSymbolAddress((void**)&ehrT,  g_ehrT);
    cudaGetSymbolAddress((void**)&critT, g_critT);
    cudaGetSymbolAddress((void**)&WaT,   g_WaT);
    cudaGetSymbolAddress((void**)&WrT,   g_WrT);
    cudaGetSymbolAddress((void**)&r1p,   g_r1p);
    cudaGetSymbolAddress((void**)&r2p,   g_r2p);
    cudaGetSymbolAddress((void**)&cmx,   g_cmx);
    cudaGetSymbolAddress((void**)&cinv,  g_cinv);

    const long LCD = (long)LCDIM * DDIM;   // 65536
    const long LED = (long)LEDIM * DDIM;   // 262144
    const long LCE = (long)LCDIM * LEDIM;  // 262144

    dim3 tb(32, 8);

    // pre-transposes (weights + activations)
    transpose_k<<<dim3(8, 8, 1),  tb>>>(Wa, WaT, DDIM, DDIM, 0, 0);
    transpose_k<<<dim3(8, 16, 1), tb>>>(Wr, WrT, 2 * DDIM, DDIM, 0, 0);
    transpose_k<<<dim3(8, 32, BB), tb>>>(ehr, ehrT, LEDIM, DDIM, LED, LED);
    transpose_k<<<dim3(8, 8, BB),  tb>>>(criteria, critT, LCDIM, DDIM, LCD, LCD);

    // c = relu(criteria @ Wa + ba)
    gemm_tc<<<dim3(DDIM / BN, (BB * LCDIM) / BM, 1), 256>>>(
        criteria, nullptr, 0, WaT, ba, c, BB * LCDIM, DDIM, DDIM,
        DDIM, 0, DDIM, 0, 0, 1);

    // e = relu(ehr @ Wa + ba)
    gemm_tc<<<dim3(DDIM / BN, (BB * LEDIM) / BM, 1), 256>>>(
        ehr, nullptr, 0, WaT, ba, e, BB * LEDIM, DDIM, DDIM,
        DDIM, 0, DDIM, 0, 0, 1);

    // align[b] = c[b] @ e[b]^T   (B = e, n-major naturally)
    gemm_tc<<<dim3(LEDIM / BN, LCDIM / BM, BB), 256>>>(
        c, nullptr, 0, e, nullptr, al, LCDIM, LEDIM, DDIM,
        DDIM, LCD, DDIM, LED, LCE, 0);

    // beta stats + transposed write (before alpha clobbers align)
    colstats_kernel<<<BB * (LEDIM / 256), 256>>>(al, cmask, cmx, cinv);
    betaT_kernel<<<dim3(LEDIM / 32, LCDIM / 32, BB), tb>>>(al, beT, cmask, cmx, cinv);

    // alpha in-place
    alpha_kernel<<<BB * LCDIM, 256>>>(al, emask);

    // att_c[b] = alpha[b] @ ehr[b]   (B = ehrT)
    gemm_tc<<<dim3(DDIM / BN, LCDIM / BM, BB), 256>>>(
        al, nullptr, 0, ehrT, nullptr, attc, LCDIM, DDIM, LEDIM,
        LEDIM, LCE, LEDIM, LED, LCD, 0);

    // att_e[b] = beta[b]^T @ criteria[b]   (A = betaT, B = critT)
    gemm_tc<<<dim3(DDIM / BN, LEDIM / BM, BB), 256>>>(
        beT, nullptr, 0, critT, nullptr, atte, LEDIM, DDIM, LCDIM,
        LCDIM, LCE, LCDIM, LCD, LED, 0);

    // r1-pre (reuse g_c) = relu([attc, criteria] @ Wr + br), fused concat K=512
    gemm_tc<<<dim3(DDIM / BN, (BB * LCDIM) / BM, 1), 256>>>(
        attc, criteria, DDIM, WrT, br, c, BB * LCDIM, DDIM, 2 * DDIM,
        DDIM, 0, 2 * DDIM, 0, 0, 1);

    // r2-pre (reuse g_e) = relu([atte, ehr] @ Wr + br)
    gemm_tc<<<dim3(DDIM / BN, (BB * LEDIM) / BM, 1), 256>>>(
        atte, ehr, DDIM, WrT, br, e, BB * LEDIM, DDIM, 2 * DDIM,
        DDIM, 0, 2 * DDIM, 0, 0, 1);

    // r1/r2 partial sums
    reduce_kernel<<<dim3(BB, 4), 256>>>(c, r1p, LCDIM);
    reduce_kernel<<<dim3(BB, 4), 256>>>(e, r2p, LEDIM);

    final_kernel<<<BB, 512>>>(r1p, r2p, Wm, bm, Wo, bo, (float*)d_out);
}